// round 10
// baseline (speedup 1.0000x reference)
#include <cuda_runtime.h>
#include <cuda_fp16.h>
#include <cstdint>

#define NF      2560
#define TW      16
#define HWDIM   9216
#define BT      1920
#define T_LEN   240
#define BATCH   8

#define BM      128     // bt rows per CTA (M)
#define BNF     128     // filters per CTA (N)
#define KC      32      // K elements per stage
#define NCHUNK  288     // HWDIM / KC
#define NSTAGE  4
#define PADROWB 80      // bytes per smem row (32 halves = 64B + 16B pad)
#define OFF_A   0
#define OFF_B   (128 * PADROWB)          // 10240
#define STG_BYTES (256 * PADROWB)        // 20480
#define SMEM_DYN  (NSTAGE * STG_BYTES)   // 81920

// fp16 copies of inputs (filled by convert kernel)
__device__ __half x_h[BT * HWDIM];
__device__ __half ws_h[NF * HWDIM];
__device__ __half wc_h[NF * HWDIM];
// intermediate g_sin / g_cos, layout [bt][f]
__device__ float g_buf0[BT * NF];
__device__ float g_buf1[BT * NF];

// ---------------------------------------------------------------------------
__device__ __forceinline__ unsigned smem_u32(const void* p) {
    return (unsigned)__cvta_generic_to_shared(p);
}
__device__ __forceinline__ void cp_async16(unsigned saddr, const void* gaddr) {
    asm volatile("cp.async.cg.shared.global [%0], [%1], 16;\n" :: "r"(saddr), "l"(gaddr));
}
__device__ __forceinline__ void ldsm_x4(uint32_t* r, unsigned addr) {
    asm volatile("ldmatrix.sync.aligned.m8n8.x4.shared.b16 {%0,%1,%2,%3}, [%4];"
                 : "=r"(r[0]), "=r"(r[1]), "=r"(r[2]), "=r"(r[3]) : "r"(addr));
}
// fp16 accumulator MMA: C/D = 2 x f16x2 regs
__device__ __forceinline__ void mma_f16acc(uint32_t* c, const uint32_t* a, const uint32_t* b) {
    asm volatile(
        "mma.sync.aligned.m16n8k16.row.col.f16.f16.f16.f16 "
        "{%0,%1}, {%2,%3,%4,%5}, {%6,%7}, {%0,%1};\n"
        : "+r"(c[0]), "+r"(c[1])
        : "r"(a[0]), "r"(a[1]), "r"(a[2]), "r"(a[3]), "r"(b[0]), "r"(b[1]));
}

// ---------------------------------------------------------------------------
// Kernel 0: fp32 -> fp16 conversion for x, w_s_sin, w_s_cos in ONE launch.
// ---------------------------------------------------------------------------
#define NX4 (BT * HWDIM / 4)
#define NW4 (NF * HWDIM / 4)
__global__ void __launch_bounds__(256)
f2h_all_kernel(const float* __restrict__ x,
               const float* __restrict__ wsin,
               const float* __restrict__ wcos) {
    int i = blockIdx.x * 256 + threadIdx.x;
    const float* src;
    __half* dst;
    int j;
    if (i < NX4)                 { src = x;    dst = x_h;  j = i; }
    else if (i < NX4 + NW4)      { src = wsin; dst = ws_h; j = i - NX4; }
    else if (i < NX4 + 2 * NW4)  { src = wcos; dst = wc_h; j = i - NX4 - NW4; }
    else return;
    float4 v = reinterpret_cast<const float4*>(src)[j];
    reinterpret_cast<__half2*>(dst)[2 * j]     = __floats2half2_rn(v.x, v.y);
    reinterpret_cast<__half2*>(dst)[2 * j + 1] = __floats2half2_rn(v.z, v.w);
}

// ---------------------------------------------------------------------------
// Kernel 1: spatial GEMM with fp16 ACCUMULATORS (promoted to f32 every 4
// K-chunks = K group of 128). 128 threads, 4 warps (2m x 2n), warp tile
// 64x64, CTA tile 128x128, KC=32, 4-stage cp.async, 2 CTAs/SM.
//   g[m, f] = sum_k x[m,k] * w[f,k]
// blockIdx.z: 0 -> ws_h -> g_buf0, 1 -> wc_h -> g_buf1.
// ---------------------------------------------------------------------------
__global__ void __launch_bounds__(128, 2)
spatial_gemm_fp16(int dummy) {
    extern __shared__ __align__(1024) char smem[];
    const unsigned smem_base = smem_u32(smem);
    const int tid = threadIdx.x;
    const int n0 = blockIdx.x * BNF;   // filter base
    const int m0 = blockIdx.y * BM;    // bt base
    const __half* wmat = blockIdx.z ? wc_h : ws_h;
    float* gout = blockIdx.z ? g_buf1 : g_buf0;

    const int lane = tid & 31;
    const int warp = tid >> 5;
    const int wm = (warp & 1) * 64;    // 2 m-warps
    const int wn = (warp >> 1) * 64;   // 2 n-warps

    float acc[4][8][4];                // f32 accumulators
    uint32_t acch[4][8][2];            // f16x2 group accumulators
    #pragma unroll
    for (int i = 0; i < 4; i++)
        #pragma unroll
        for (int j = 0; j < 8; j++) {
            #pragma unroll
            for (int k = 0; k < 4; k++) acc[i][j][k] = 0.f;
            acch[i][j][0] = 0u; acch[i][j][1] = 0u;
        }

    // loader: 128 threads; row = tid>>2 (0..31, step 32 x4), seg = tid&3
    const int lrow = tid >> 2;
    const int seg = tid & 3;
    const __half* ga = x_h  + (size_t)(m0 + lrow) * HWDIM + seg * 8;
    const __half* gb = wmat + (size_t)(n0 + lrow) * HWDIM + seg * 8;
    const unsigned lsm = smem_base + lrow * PADROWB + seg * 16;

    auto load_stage = [&](int kt, int slot) {
        const unsigned sb = lsm + slot * STG_BYTES;
        const __half* pa = ga + kt * KC;
        const __half* pb = gb + kt * KC;
        #pragma unroll
        for (int i = 0; i < 4; i++) {
            cp_async16(sb + OFF_A + i * 32 * PADROWB, pa + (size_t)i * 32 * HWDIM);
            cp_async16(sb + OFF_B + i * 32 * PADROWB, pb + (size_t)i * 32 * HWDIM);
        }
        asm volatile("cp.async.commit_group;\n");
    };

    // ldmatrix per-lane byte offsets within a stage
    const int mrow = wm + (lane & 7) + 8 * ((lane >> 3) & 1);
    const int akb  = (lane >> 4) * 16;
    unsigned aoff[4];
    #pragma unroll
    for (int mt = 0; mt < 4; mt++) aoff[mt] = (mrow + mt * 16) * PADROWB + akb;

    const int nrow = wn + (lane & 7) + 8 * (lane >> 4);
    const int bkb  = ((lane >> 3) & 1) * 16;
    unsigned boff[4];
    #pragma unroll
    for (int p = 0; p < 4; p++) boff[p] = (nrow + p * 16) * PADROWB + bkb;

    // prologue: fill 3 of 4 stages
    load_stage(0, 0);
    load_stage(1, 1);
    load_stage(2, 2);

    for (int kt = 0; kt < NCHUNK; kt++) {
        if (kt < NCHUNK - 2)       asm volatile("cp.async.wait_group 2;\n");
        else if (kt == NCHUNK - 2) asm volatile("cp.async.wait_group 1;\n");
        else                       asm volatile("cp.async.wait_group 0;\n");
        __syncthreads();
        if (kt + 3 < NCHUNK) load_stage(kt + 3, (kt + 3) % NSTAGE);

        const unsigned sb = smem_base + (kt % NSTAGE) * STG_BYTES;
        #pragma unroll
        for (int kk = 0; kk < 2; kk++) {
            const unsigned kb = kk * 32;
            uint32_t a[4][4], b[4][4];
            #pragma unroll
            for (int mt = 0; mt < 4; mt++) ldsm_x4(a[mt], sb + OFF_A + aoff[mt] + kb);
            #pragma unroll
            for (int p = 0; p < 4; p++)  ldsm_x4(b[p], sb + OFF_B + boff[p] + kb);
            #pragma unroll
            for (int mt = 0; mt < 4; mt++)
                #pragma unroll
                for (int nt = 0; nt < 8; nt++)
                    mma_f16acc(acch[mt][nt], a[mt], &b[nt >> 1][(nt & 1) * 2]);
        }

        // promote f16 group accumulators to f32 every 4 chunks (K group 128)
        if ((kt & 3) == 3) {
            #pragma unroll
            for (int mt = 0; mt < 4; mt++)
                #pragma unroll
                for (int nt = 0; nt < 8; nt++) {
                    float2 lo = __half22float2(
                        *reinterpret_cast<__half2*>(&acch[mt][nt][0]));
                    float2 hi = __half22float2(
                        *reinterpret_cast<__half2*>(&acch[mt][nt][1]));
                    acc[mt][nt][0] += lo.x; acc[mt][nt][1] += lo.y;
                    acc[mt][nt][2] += hi.x; acc[mt][nt][3] += hi.y;
                    acch[mt][nt][0] = 0u;   acch[mt][nt][1] = 0u;
                }
        }
        // single barrier per iter: next iter's top barrier is the WAR guard
    }

    // epilogue (NCHUNK % 4 == 0, so the last promote already ran)
    #pragma unroll
    for (int mt = 0; mt < 4; mt++) {
        #pragma unroll
        for (int nt = 0; nt < 8; nt++) {
            int m = m0 + wm + mt * 16 + (lane >> 2);
            int n = n0 + wn + nt * 8 + (lane & 3) * 2;
            *reinterpret_cast<float2*>(&gout[(size_t)m * NF + n]) =
                make_float2(acc[mt][nt][0], acc[mt][nt][1]);
            *reinterpret_cast<float2*>(&gout[(size_t)(m + 8) * NF + n]) =
                make_float2(acc[mt][nt][2], acc[mt][nt][3]);
        }
    }
}

// ---------------------------------------------------------------------------
// Kernel 2: depthwise temporal convs + energy. Ring-buffer sliding window,
// T split into 5 chunks of 48.
// ---------------------------------------------------------------------------
__global__ void __launch_bounds__(256)
temporal_kernel(const float* __restrict__ wt_sin_g,
                const float* __restrict__ wt_cos_g,
                float* __restrict__ out) {
    const int f = blockIdx.x * 256 + threadIdx.x;
    const int b = blockIdx.y;
    const int t0 = blockIdx.z * 48;

    float wts[TW], wtc[TW];
    #pragma unroll
    for (int j = 0; j < TW; j++) {
        wts[j] = wt_sin_g[f * TW + j];
        wtc[j] = wt_cos_g[f * TW + j];
    }

    const float* gs = g_buf0 + (size_t)b * T_LEN * NF + f;
    const float* gc = g_buf1 + (size_t)b * T_LEN * NF + f;
    float* op = out + (size_t)b * T_LEN * NF + f;

    float rs[TW], rc[TW];
    #pragma unroll
    for (int j = 0; j < TW; j++) {
        int t = t0 - 8 + j;
        int i = t & 15;
        rs[i] = (t >= 0) ? gs[t * NF] : 0.f;
        rc[i] = (t >= 0) ? gc[t * NF] : 0.f;
    }

    #pragma unroll 16
    for (int tt = 0; tt < 48; tt++) {
        const int t = t0 + tt;
        float t1 = 0.f, t2 = 0.f, t3 = 0.f, t4 = 0.f;
        #pragma unroll
        for (int j = 0; j < TW; j++) {
            int i = (tt - 8 + j) & 15;
            t1 += rs[i] * wtc[j];
            t2 += rc[i] * wts[j];
            t3 += rc[i] * wtc[j];
            t4 += rs[i] * wts[j];
        }
        float resp_s = t1 + t2;
        float resp_c = t3 - t4;
        float v = resp_s * resp_s + resp_c * resp_c;
        op[t * NF] = logf(sqrtf(v) + 1e-5f);

        int tn = t + 8;
        int i = tn & 15;
        rs[i] = (tn < T_LEN) ? gs[tn * NF] : 0.f;
        rc[i] = (tn < T_LEN) ? gc[tn * NF] : 0.f;
    }
}

extern "C" void kernel_launch(void* const* d_in, const int* in_sizes, int n_in,
                              void* d_out, int out_size) {
    const float* x       = (const float*)d_in[0];
    const float* w_s_sin = (const float*)d_in[1];
    const float* w_s_cos = (const float*)d_in[2];
    const float* w_t_sin = (const float*)d_in[3];
    const float* w_t_cos = (const float*)d_in[4];
    float* out = (float*)d_out;

    const int ntot = NX4 + 2 * NW4;
    f2h_all_kernel<<<(ntot + 255) / 256, 256>>>(x, w_s_sin, w_s_cos);

    cudaFuncSetAttribute(spatial_gemm_fp16,
                         cudaFuncAttributeMaxDynamicSharedMemorySize, SMEM_DYN);

    dim3 g1(NF / BNF, BT / BM, 2);     // (20, 15, 2) = 600 CTAs, 2/SM
    spatial_gemm_fp16<<<g1, 128, SMEM_DYN>>>(0);

    dim3 g2(NF / 256, BATCH, T_LEN / 48);   // (10, 8, 5)
    temporal_kernel<<<g2, 256>>>(w_t_sin, w_t_cos, out);
}

// round 11
// speedup vs baseline: 1.0610x; 1.0610x over previous
#include <cuda_runtime.h>
#include <cuda_fp16.h>
#include <cstdint>

#define NF      2560
#define TW      16
#define HWDIM   9216
#define BT      1920
#define T_LEN   240
#define BATCH   8

#define BM      128     // bt rows per CTA (M)
#define BNF     128     // filters per CTA (N)
#define KC      32      // K elements per stage
#define NCHUNK  288     // HWDIM / KC
#define PADROWB 80      // bytes per smem row (32 halves = 64B + 16B pad)
#define OFF_A   0
#define OFF_B   (128 * PADROWB)          // 10240
#define STG_BYTES (256 * PADROWB)        // 20480
#define SMEM_DYN  (3 * STG_BYTES)        // 61440

#define TCH     16      // temporal chunk length

// fp16 copies of inputs (filled by convert kernel)
__device__ __half x_h[BT * HWDIM];
__device__ __half ws_h[NF * HWDIM];
__device__ __half wc_h[NF * HWDIM];
// intermediate g_sin / g_cos, layout [bt][f]
__device__ float g_buf0[BT * NF];
__device__ float g_buf1[BT * NF];

// ---------------------------------------------------------------------------
__device__ __forceinline__ unsigned smem_u32(const void* p) {
    return (unsigned)__cvta_generic_to_shared(p);
}
__device__ __forceinline__ void cp_async16(unsigned saddr, const void* gaddr) {
    asm volatile("cp.async.cg.shared.global [%0], [%1], 16;\n" :: "r"(saddr), "l"(gaddr));
}
__device__ __forceinline__ void ldsm_x4(uint32_t* r, unsigned addr) {
    asm volatile("ldmatrix.sync.aligned.m8n8.x4.shared.b16 {%0,%1,%2,%3}, [%4];"
                 : "=r"(r[0]), "=r"(r[1]), "=r"(r[2]), "=r"(r[3]) : "r"(addr));
}
__device__ __forceinline__ void mma_fp16(float* c, const uint32_t* a, const uint32_t* b) {
    asm volatile(
        "mma.sync.aligned.m16n8k16.row.col.f32.f16.f16.f32 "
        "{%0,%1,%2,%3}, {%4,%5,%6,%7}, {%8,%9}, {%0,%1,%2,%3};\n"
        : "+f"(c[0]), "+f"(c[1]), "+f"(c[2]), "+f"(c[3])
        : "r"(a[0]), "r"(a[1]), "r"(a[2]), "r"(a[3]), "r"(b[0]), "r"(b[1]));
}

// ---------------------------------------------------------------------------
// Kernel 0: fp32 -> fp16 conversion for x, w_s_sin, w_s_cos in ONE launch.
// ---------------------------------------------------------------------------
#define NX4 (BT * HWDIM / 4)
#define NW4 (NF * HWDIM / 4)
__global__ void __launch_bounds__(256)
f2h_all_kernel(const float* __restrict__ x,
               const float* __restrict__ wsin,
               const float* __restrict__ wcos) {
    int i = blockIdx.x * 256 + threadIdx.x;
    const float* src;
    __half* dst;
    int j;
    if (i < NX4)                 { src = x;    dst = x_h;  j = i; }
    else if (i < NX4 + NW4)      { src = wsin; dst = ws_h; j = i - NX4; }
    else if (i < NX4 + 2 * NW4)  { src = wcos; dst = wc_h; j = i - NX4 - NW4; }
    else return;
    float4 v = reinterpret_cast<const float4*>(src)[j];
    reinterpret_cast<__half2*>(dst)[2 * j]     = __floats2half2_rn(v.x, v.y);
    reinterpret_cast<__half2*>(dst)[2 * j + 1] = __floats2half2_rn(v.z, v.w);
}

// ---------------------------------------------------------------------------
// Kernel 1: spatial GEMM, fp16 mma.sync, KC=32, 3-stage cp.async, 2 CTAs/SM.
// (exact round-4 configuration — best measured: GEMM ~552us)
//   g[m, f] = sum_k x[m,k] * w[f,k]
// Block tile 128(m) x 128(f), 256 threads, warp tile 64m x 32f.
// blockIdx.z: 0 -> ws_h -> g_buf0, 1 -> wc_h -> g_buf1.
// ---------------------------------------------------------------------------
__global__ void __launch_bounds__(256, 2)
spatial_gemm_fp16(int dummy) {
    extern __shared__ __align__(1024) char smem[];
    const unsigned smem_base = smem_u32(smem);
    const int tid = threadIdx.x;
    const int n0 = blockIdx.x * BNF;   // filter base
    const int m0 = blockIdx.y * BM;    // bt base
    const __half* wmat = blockIdx.z ? wc_h : ws_h;
    float* gout = blockIdx.z ? g_buf1 : g_buf0;

    const int lane = tid & 31;
    const int warp = tid >> 5;
    const int wm = (warp & 1) * 64;
    const int wn = (warp >> 1) * 32;

    float acc[4][4][4];
    #pragma unroll
    for (int i = 0; i < 4; i++)
        #pragma unroll
        for (int j = 0; j < 4; j++)
            #pragma unroll
            for (int k = 0; k < 4; k++) acc[i][j][k] = 0.f;

    // loader: row = tid>>2 (0..63, +64), seg = tid&3 (16B each); 2 xfers/array
    const int lrow = tid >> 2;
    const int seg = tid & 3;
    const __half* ga = x_h  + (size_t)(m0 + lrow) * HWDIM + seg * 8;
    const __half* gb = wmat + (size_t)(n0 + lrow) * HWDIM + seg * 8;
    const unsigned lsm = smem_base + lrow * PADROWB + seg * 16;

    auto load_stage = [&](int kt, int slot) {
        const unsigned sb = lsm + slot * STG_BYTES;
        const __half* pa = ga + kt * KC;
        const __half* pb = gb + kt * KC;
        #pragma unroll
        for (int i = 0; i < 2; i++) {
            cp_async16(sb + OFF_A + i * 64 * PADROWB, pa + (size_t)i * 64 * HWDIM);
            cp_async16(sb + OFF_B + i * 64 * PADROWB, pb + (size_t)i * 64 * HWDIM);
        }
        asm volatile("cp.async.commit_group;\n");
    };

    // ldmatrix per-lane byte offsets within a stage
    const int mrow = wm + (lane & 7) + 8 * ((lane >> 3) & 1);
    const int akb  = (lane >> 4) * 16;
    unsigned aoff[4];
    #pragma unroll
    for (int mt = 0; mt < 4; mt++) aoff[mt] = (mrow + mt * 16) * PADROWB + akb;

    const int nrow = wn + (lane & 7) + 8 * (lane >> 4);
    const int bkb  = ((lane >> 3) & 1) * 16;
    unsigned boff[2];
    #pragma unroll
    for (int p = 0; p < 2; p++) boff[p] = (nrow + p * 16) * PADROWB + bkb;

    // prologue
    load_stage(0, 0);
    load_stage(1, 1);

    for (int kt = 0; kt < NCHUNK; kt++) {
        if (kt < NCHUNK - 1) asm volatile("cp.async.wait_group 1;\n");
        else                 asm volatile("cp.async.wait_group 0;\n");
        __syncthreads();
        if (kt + 2 < NCHUNK) load_stage(kt + 2, (kt + 2) % 3);

        const unsigned sb = smem_base + (kt % 3) * STG_BYTES;
        #pragma unroll
        for (int kk = 0; kk < 2; kk++) {
            const unsigned kb = kk * 32;
            uint32_t a[4][4], b[2][4];
            #pragma unroll
            for (int mt = 0; mt < 4; mt++) ldsm_x4(a[mt], sb + OFF_A + aoff[mt] + kb);
            #pragma unroll
            for (int p = 0; p < 2; p++) ldsm_x4(b[p], sb + OFF_B + boff[p] + kb);
            #pragma unroll
            for (int mt = 0; mt < 4; mt++)
                #pragma unroll
                for (int nt = 0; nt < 4; nt++)
                    mma_fp16(acc[mt][nt], a[mt], &b[nt >> 1][(nt & 1) * 2]);
        }
        __syncthreads();
    }

    // epilogue
    #pragma unroll
    for (int mt = 0; mt < 4; mt++) {
        #pragma unroll
        for (int nt = 0; nt < 4; nt++) {
            int m = m0 + wm + mt * 16 + (lane >> 2);
            int n = n0 + wn + nt * 8 + (lane & 3) * 2;
            *reinterpret_cast<float2*>(&gout[(size_t)m * NF + n]) =
                make_float2(acc[mt][nt][0], acc[mt][nt][1]);
            *reinterpret_cast<float2*>(&gout[(size_t)(m + 8) * NF + n]) =
                make_float2(acc[mt][nt][2], acc[mt][nt][3]);
        }
    }
}

// ---------------------------------------------------------------------------
// Kernel 2: depthwise temporal convs + energy. Ring-buffer sliding window,
// T split into 15 chunks of 16 (3x concurrency vs 48-chunks) + fast log.
// ---------------------------------------------------------------------------
__global__ void __launch_bounds__(256)
temporal_kernel(const float* __restrict__ wt_sin_g,
                const float* __restrict__ wt_cos_g,
                float* __restrict__ out) {
    const int f = blockIdx.x * 256 + threadIdx.x;
    const int b = blockIdx.y;
    const int t0 = blockIdx.z * TCH;

    float wts[TW], wtc[TW];
    #pragma unroll
    for (int j = 0; j < TW; j++) {
        wts[j] = wt_sin_g[f * TW + j];
        wtc[j] = wt_cos_g[f * TW + j];
    }

    const float* gs = g_buf0 + (size_t)b * T_LEN * NF + f;
    const float* gc = g_buf1 + (size_t)b * T_LEN * NF + f;
    float* op = out + (size_t)b * T_LEN * NF + f;

    // ring[i] holds g[t'] with t' & 15 == i, covering [t-8, t+7]
    float rs[TW], rc[TW];
    #pragma unroll
    for (int j = 0; j < TW; j++) {
        int t = t0 - 8 + j;
        int i = t & 15;
        rs[i] = (t >= 0) ? gs[t * NF] : 0.f;
        rc[i] = (t >= 0) ? gc[t * NF] : 0.f;
    }

    #pragma unroll
    for (int tt = 0; tt < TCH; tt++) {
        const int t = t0 + tt;
        float t1 = 0.f, t2 = 0.f, t3 = 0.f, t4 = 0.f;
        #pragma unroll
        for (int j = 0; j < TW; j++) {
            int i = (tt - 8 + j) & 15;     // t0 % 16 == 0 -> static indices
            t1 += rs[i] * wtc[j];
            t2 += rc[i] * wts[j];
            t3 += rc[i] * wtc[j];
            t4 += rs[i] * wts[j];
        }
        float resp_s = t1 + t2;
        float resp_c = t3 - t4;
        float v = resp_s * resp_s + resp_c * resp_c;
        op[t * NF] = __logf(sqrtf(v) + 1e-5f);

        int tn = t + 8;
        int i = tn & 15;
        rs[i] = (tn < T_LEN) ? gs[tn * NF] : 0.f;
        rc[i] = (tn < T_LEN) ? gc[tn * NF] : 0.f;
    }
}

extern "C" void kernel_launch(void* const* d_in, const int* in_sizes, int n_in,
                              void* d_out, int out_size) {
    const float* x       = (const float*)d_in[0];
    const float* w_s_sin = (const float*)d_in[1];
    const float* w_s_cos = (const float*)d_in[2];
    const float* w_t_sin = (const float*)d_in[3];
    const float* w_t_cos = (const float*)d_in[4];
    float* out = (float*)d_out;

    const int ntot = NX4 + 2 * NW4;
    f2h_all_kernel<<<(ntot + 255) / 256, 256>>>(x, w_s_sin, w_s_cos);

    cudaFuncSetAttribute(spatial_gemm_fp16,
                         cudaFuncAttributeMaxDynamicSharedMemorySize, SMEM_DYN);

    dim3 g1(NF / BNF, BT / BM, 2);     // (20, 15, 2) = 600 CTAs, 2/SM
    spatial_gemm_fp16<<<g1, 256, SMEM_DYN>>>(0);

    dim3 g2(NF / 256, BATCH, T_LEN / TCH);   // (10, 8, 15) = 1200 blocks
    temporal_kernel<<<g2, 256>>>(w_t_sin, w_t_cos, out);
}

// round 13
// speedup vs baseline: 1.0669x; 1.0056x over previous
#include <cuda_runtime.h>
#include <cuda_fp16.h>
#include <cstdint>

#define NF      2560
#define TW      16
#define HWDIM   9216
#define BT      1920
#define T_LEN   240
#define BATCH   8

#define BM      128     // bt rows per CTA (M)
#define BNF     128     // filters per CTA (N)
#define KC      32      // K elements per stage
#define NCHUNK  288     // HWDIM / KC
#define PADROWB 80      // bytes per smem row (32 halves = 64B + 16B pad)
#define OFF_A   0
#define OFF_B   (128 * PADROWB)          // 10240
#define STG_BYTES (256 * PADROWB)        // 20480
#define SMEM_DYN  (3 * STG_BYTES)        // 61440

#define TCH     16      // temporal chunk length

// fp16 copies of inputs (filled by convert kernel)
__device__ __half x_h[BT * HWDIM];
__device__ __half ws_h[NF * HWDIM];
__device__ __half wc_h[NF * HWDIM];
// intermediate g_sin / g_cos, layout [bt][f]
__device__ float g_buf0[BT * NF];
__device__ float g_buf1[BT * NF];

// ---------------------------------------------------------------------------
__device__ __forceinline__ unsigned smem_u32(const void* p) {
    return (unsigned)__cvta_generic_to_shared(p);
}
__device__ __forceinline__ void cp_async16(unsigned saddr, const void* gaddr) {
    asm volatile("cp.async.cg.shared.global [%0], [%1], 16;\n" :: "r"(saddr), "l"(gaddr));
}
__device__ __forceinline__ void ldsm_x4(uint32_t* r, unsigned addr) {
    asm volatile("ldmatrix.sync.aligned.m8n8.x4.shared.b16 {%0,%1,%2,%3}, [%4];"
                 : "=r"(r[0]), "=r"(r[1]), "=r"(r[2]), "=r"(r[3]) : "r"(addr));
}
__device__ __forceinline__ void mma_fp16(float* c, const uint32_t* a, const uint32_t* b) {
    asm volatile(
        "mma.sync.aligned.m16n8k16.row.col.f32.f16.f16.f32 "
        "{%0,%1,%2,%3}, {%4,%5,%6,%7}, {%8,%9}, {%0,%1,%2,%3};\n"
        : "+f"(c[0]), "+f"(c[1]), "+f"(c[2]), "+f"(c[3])
        : "r"(a[0]), "r"(a[1]), "r"(a[2]), "r"(a[3]), "r"(b[0]), "r"(b[1]));
}

// ---------------------------------------------------------------------------
// Kernel 0: fp32 -> fp16 conversion for x, w_s_sin, w_s_cos in ONE launch.
// 2 independent float4 per thread (MLP=2).
// ---------------------------------------------------------------------------
#define NX4 (BT * HWDIM / 4)             // 4423680
#define NW4 (NF * HWDIM / 4)             // 5898240
#define NTOT4 (NX4 + 2 * NW4)            // 16220160
#define NHALF4 (NTOT4 / 2)               // 8110080

__device__ __forceinline__ void f2h_one(int j,
                                        const float* __restrict__ x,
                                        const float* __restrict__ wsin,
                                        const float* __restrict__ wcos) {
    const float* src;
    __half* dst;
    if (j < NX4)                { src = x;    dst = x_h; }
    else if (j < NX4 + NW4)     { src = wsin; dst = ws_h; j -= NX4; }
    else                        { src = wcos; dst = wc_h; j -= NX4 + NW4; }
    float4 v = reinterpret_cast<const float4*>(src)[j];
    reinterpret_cast<__half2*>(dst)[2 * j]     = __floats2half2_rn(v.x, v.y);
    reinterpret_cast<__half2*>(dst)[2 * j + 1] = __floats2half2_rn(v.z, v.w);
}

__global__ void __launch_bounds__(256)
f2h_all_kernel(const float* __restrict__ x,
               const float* __restrict__ wsin,
               const float* __restrict__ wcos) {
    int i = blockIdx.x * 256 + threadIdx.x;
    if (i < NHALF4) {
        f2h_one(i, x, wsin, wcos);
        f2h_one(i + NHALF4, x, wsin, wcos);
    }
}

// ---------------------------------------------------------------------------
// Kernel 1: spatial GEMM, fp16 mma.sync, KC=32, 3-stage cp.async, 2 CTAs/SM.
// (frozen round-4 configuration — best measured across 7 variants)
//   g[m, f] = sum_k x[m,k] * w[f,k]
// Block tile 128(m) x 128(f), 256 threads, warp tile 64m x 32f.
// blockIdx.z: 0 -> ws_h -> g_buf0, 1 -> wc_h -> g_buf1.
// ---------------------------------------------------------------------------
__global__ void __launch_bounds__(256, 2)
spatial_gemm_fp16(int dummy) {
    extern __shared__ __align__(1024) char smem[];
    const unsigned smem_base = smem_u32(smem);
    const int tid = threadIdx.x;
    const int n0 = blockIdx.x * BNF;   // filter base
    const int m0 = blockIdx.y * BM;    // bt base
    const __half* wmat = blockIdx.z ? wc_h : ws_h;
    float* gout = blockIdx.z ? g_buf1 : g_buf0;

    const int lane = tid & 31;
    const int warp = tid >> 5;
    const int wm = (warp & 1) * 64;
    const int wn = (warp >> 1) * 32;

    float acc[4][4][4];
    #pragma unroll
    for (int i = 0; i < 4; i++)
        #pragma unroll
        for (int j = 0; j < 4; j++)
            #pragma unroll
            for (int k = 0; k < 4; k++) acc[i][j][k] = 0.f;

    // loader: row = tid>>2 (0..63, +64), seg = tid&3 (16B each); 2 xfers/array
    const int lrow = tid >> 2;
    const int seg = tid & 3;
    const __half* ga = x_h  + (size_t)(m0 + lrow) * HWDIM + seg * 8;
    const __half* gb = wmat + (size_t)(n0 + lrow) * HWDIM + seg * 8;
    const unsigned lsm = smem_base + lrow * PADROWB + seg * 16;

    auto load_stage = [&](int kt, int slot) {
        const unsigned sb = lsm + slot * STG_BYTES;
        const __half* pa = ga + kt * KC;
        const __half* pb = gb + kt * KC;
        #pragma unroll
        for (int i = 0; i < 2; i++) {
            cp_async16(sb + OFF_A + i * 64 * PADROWB, pa + (size_t)i * 64 * HWDIM);
            cp_async16(sb + OFF_B + i * 64 * PADROWB, pb + (size_t)i * 64 * HWDIM);
        }
        asm volatile("cp.async.commit_group;\n");
    };

    // ldmatrix per-lane byte offsets within a stage
    const int mrow = wm + (lane & 7) + 8 * ((lane >> 3) & 1);
    const int akb  = (lane >> 4) * 16;
    unsigned aoff[4];
    #pragma unroll
    for (int mt = 0; mt < 4; mt++) aoff[mt] = (mrow + mt * 16) * PADROWB + akb;

    const int nrow = wn + (lane & 7) + 8 * (lane >> 4);
    const int bkb  = ((lane >> 3) & 1) * 16;
    unsigned boff[2];
    #pragma unroll
    for (int p = 0; p < 2; p++) boff[p] = (nrow + p * 16) * PADROWB + bkb;

    // prologue
    load_stage(0, 0);
    load_stage(1, 1);

    for (int kt = 0; kt < NCHUNK; kt++) {
        if (kt < NCHUNK - 1) asm volatile("cp.async.wait_group 1;\n");
        else                 asm volatile("cp.async.wait_group 0;\n");
        __syncthreads();
        if (kt + 2 < NCHUNK) load_stage(kt + 2, (kt + 2) % 3);

        const unsigned sb = smem_base + (kt % 3) * STG_BYTES;
        #pragma unroll
        for (int kk = 0; kk < 2; kk++) {
            const unsigned kb = kk * 32;
            uint32_t a[4][4], b[2][4];
            #pragma unroll
            for (int mt = 0; mt < 4; mt++) ldsm_x4(a[mt], sb + OFF_A + aoff[mt] + kb);
            #pragma unroll
            for (int p = 0; p < 2; p++) ldsm_x4(b[p], sb + OFF_B + boff[p] + kb);
            #pragma unroll
            for (int mt = 0; mt < 4; mt++)
                #pragma unroll
                for (int nt = 0; nt < 4; nt++)
                    mma_fp16(acc[mt][nt], a[mt], &b[nt >> 1][(nt & 1) * 2]);
        }
        __syncthreads();
    }

    // epilogue
    #pragma unroll
    for (int mt = 0; mt < 4; mt++) {
        #pragma unroll
        for (int nt = 0; nt < 4; nt++) {
            int m = m0 + wm + mt * 16 + (lane >> 2);
            int n = n0 + wn + nt * 8 + (lane & 3) * 2;
            *reinterpret_cast<float2*>(&gout[(size_t)m * NF + n]) =
                make_float2(acc[mt][nt][0], acc[mt][nt][1]);
            *reinterpret_cast<float2*>(&gout[(size_t)(m + 8) * NF + n]) =
                make_float2(acc[mt][nt][2], acc[mt][nt][3]);
        }
    }
}

// ---------------------------------------------------------------------------
// Kernel 2: depthwise temporal convs + energy, CORRECT 3-multiply complex
// form. (a+ib)(c+id) with a=gc, b=gs, c=wtc, d=wts:
//   m1 = sum (gc+gs)*wtc,  m2 = sum gc*(wts-wtc),  m3 = sum gs*(wtc+wts)
//   resp_sin = m1 + m2 = conv(gs,wtc)+conv(gc,wts)
//   resp_cos = m1 - m3 = conv(gc,wtc)-conv(gs,wts)
// 48 FMA/t instead of 64. Ring-buffer window, T in 15 chunks of 16.
// ---------------------------------------------------------------------------
__global__ void __launch_bounds__(256)
temporal_kernel(const float* __restrict__ wt_sin_g,
                const float* __restrict__ wt_cos_g,
                float* __restrict__ out) {
    const int f = blockIdx.x * 256 + threadIdx.x;
    const int b = blockIdx.y;
    const int t0 = blockIdx.z * TCH;

    float wtc[TW], wd[TW], w1[TW];
    #pragma unroll
    for (int j = 0; j < TW; j++) {
        float s = wt_sin_g[f * TW + j];
        float c = wt_cos_g[f * TW + j];
        wtc[j] = c;
        wd[j]  = s - c;     // wts - wtc
        w1[j]  = c + s;     // wtc + wts
    }

    const float* gs = g_buf0 + (size_t)b * T_LEN * NF + f;
    const float* gc = g_buf1 + (size_t)b * T_LEN * NF + f;
    float* op = out + (size_t)b * T_LEN * NF + f;

    // rings: rs = g_sin, rc = g_cos, rq = g_cos + g_sin (amortized sum)
    float rs[TW], rc[TW], rq[TW];
    #pragma unroll
    for (int j = 0; j < TW; j++) {
        int t = t0 - 8 + j;
        int i = t & 15;
        float vs = (t >= 0) ? gs[t * NF] : 0.f;
        float vc = (t >= 0) ? gc[t * NF] : 0.f;
        rs[i] = vs; rc[i] = vc; rq[i] = vc + vs;
    }

    #pragma unroll
    for (int tt = 0; tt < TCH; tt++) {
        const int t = t0 + tt;
        float m1 = 0.f, m2 = 0.f, m3 = 0.f;
        #pragma unroll
        for (int j = 0; j < TW; j++) {
            int i = (tt - 8 + j) & 15;     // t0 % 16 == 0 -> static indices
            m1 += rq[i] * wtc[j];
            m2 += rc[i] * wd[j];
            m3 += rs[i] * w1[j];
        }
        float resp_s = m1 + m2;
        float resp_c = m1 - m3;
        float v = resp_s * resp_s + resp_c * resp_c;
        op[t * NF] = __logf(sqrtf(v) + 1e-5f);

        int tn = t + 8;
        int i = tn & 15;
        float vs = (tn < T_LEN) ? gs[tn * NF] : 0.f;
        float vc = (tn < T_LEN) ? gc[tn * NF] : 0.f;
        rs[i] = vs; rc[i] = vc; rq[i] = vc + vs;
    }
}

extern "C" void kernel_launch(void* const* d_in, const int* in_sizes, int n_in,
                              void* d_out, int out_size) {
    const float* x       = (const float*)d_in[0];
    const float* w_s_sin = (const float*)d_in[1];
    const float* w_s_cos = (const float*)d_in[2];
    const float* w_t_sin = (const float*)d_in[3];
    const float* w_t_cos = (const float*)d_in[4];
    float* out = (float*)d_out;

    f2h_all_kernel<<<(NHALF4 + 255) / 256, 256>>>(x, w_s_sin, w_s_cos);

    cudaFuncSetAttribute(spatial_gemm_fp16,
                         cudaFuncAttributeMaxDynamicSharedMemorySize, SMEM_DYN);

    dim3 g1(NF / BNF, BT / BM, 2);     // (20, 15, 2) = 600 CTAs, 2/SM
    spatial_gemm_fp16<<<g1, 256, SMEM_DYN>>>(0);

    dim3 g2(NF / 256, BATCH, T_LEN / TCH);   // (10, 8, 15) = 1200 blocks
    temporal_kernel<<<g2, 256>>>(w_t_sin, w_t_cos, out);
}

// round 14
// speedup vs baseline: 1.0693x; 1.0023x over previous
#include <cuda_runtime.h>
#include <cuda_fp16.h>
#include <cstdint>

#define NF      2560
#define TW      16
#define HWDIM   9216
#define BT      1920
#define T_LEN   240
#define BATCH   8

#define BM      128     // bt rows per CTA (M)
#define BNF     128     // filters per CTA (N)
#define KC      32      // K elements per stage
#define NCHUNK  288     // HWDIM / KC
#define PADROWB 80      // bytes per smem row (32 halves = 64B + 16B pad)
#define OFF_A   0
#define OFF_B   (128 * PADROWB)          // 10240
#define STG_BYTES (256 * PADROWB)        // 20480
#define SMEM_DYN  (3 * STG_BYTES)        // 61440

#define TCH     16      // temporal chunk length

// fp16 copies of inputs (filled by convert kernel)
__device__ __half x_h[BT * HWDIM];
__device__ __half ws_h[NF * HWDIM];
__device__ __half wc_h[NF * HWDIM];
// intermediate g_sin / g_cos in fp16, layout [bt][f]
__device__ __half g_buf0[BT * NF];
__device__ __half g_buf1[BT * NF];

// ---------------------------------------------------------------------------
__device__ __forceinline__ unsigned smem_u32(const void* p) {
    return (unsigned)__cvta_generic_to_shared(p);
}
__device__ __forceinline__ void cp_async16(unsigned saddr, const void* gaddr) {
    asm volatile("cp.async.cg.shared.global [%0], [%1], 16;\n" :: "r"(saddr), "l"(gaddr));
}
__device__ __forceinline__ void ldsm_x4(uint32_t* r, unsigned addr) {
    asm volatile("ldmatrix.sync.aligned.m8n8.x4.shared.b16 {%0,%1,%2,%3}, [%4];"
                 : "=r"(r[0]), "=r"(r[1]), "=r"(r[2]), "=r"(r[3]) : "r"(addr));
}
__device__ __forceinline__ void mma_fp16(float* c, const uint32_t* a, const uint32_t* b) {
    asm volatile(
        "mma.sync.aligned.m16n8k16.row.col.f32.f16.f16.f32 "
        "{%0,%1,%2,%3}, {%4,%5,%6,%7}, {%8,%9}, {%0,%1,%2,%3};\n"
        : "+f"(c[0]), "+f"(c[1]), "+f"(c[2]), "+f"(c[3])
        : "r"(a[0]), "r"(a[1]), "r"(a[2]), "r"(a[3]), "r"(b[0]), "r"(b[1]));
}

// ---------------------------------------------------------------------------
// Kernel 0: fp32 -> fp16 conversion for x, w_s_sin, w_s_cos in ONE launch.
// 4 independent float4 per thread (MLP=4).
// ---------------------------------------------------------------------------
#define NX4 (BT * HWDIM / 4)             // 4423680
#define NW4 (NF * HWDIM / 4)             // 5898240
#define NTOT4 (NX4 + 2 * NW4)            // 16220160
#define NQ4   (NTOT4 / 4)                // 4055040

__device__ __forceinline__ void f2h_one(int j,
                                        const float* __restrict__ x,
                                        const float* __restrict__ wsin,
                                        const float* __restrict__ wcos) {
    const float* src;
    __half* dst;
    if (j < NX4)                { src = x;    dst = x_h; }
    else if (j < NX4 + NW4)     { src = wsin; dst = ws_h; j -= NX4; }
    else                        { src = wcos; dst = wc_h; j -= NX4 + NW4; }
    float4 v = reinterpret_cast<const float4*>(src)[j];
    reinterpret_cast<__half2*>(dst)[2 * j]     = __floats2half2_rn(v.x, v.y);
    reinterpret_cast<__half2*>(dst)[2 * j + 1] = __floats2half2_rn(v.z, v.w);
}

__global__ void __launch_bounds__(256)
f2h_all_kernel(const float* __restrict__ x,
               const float* __restrict__ wsin,
               const float* __restrict__ wcos) {
    int i = blockIdx.x * 256 + threadIdx.x;
    if (i < NQ4) {
        f2h_one(i, x, wsin, wcos);
        f2h_one(i + NQ4, x, wsin, wcos);
        f2h_one(i + 2 * NQ4, x, wsin, wcos);
        f2h_one(i + 3 * NQ4, x, wsin, wcos);
    }
}

// ---------------------------------------------------------------------------
// Kernel 1: spatial GEMM, fp16 mma.sync, KC=32, 3-stage cp.async, 2 CTAs/SM.
// (frozen round-4 configuration — best measured across 8 variants)
//   g[m, f] = sum_k x[m,k] * w[f,k]   (output stored fp16)
// Block tile 128(m) x 128(f), 256 threads, warp tile 64m x 32f.
// blockIdx.z: 0 -> ws_h -> g_buf0, 1 -> wc_h -> g_buf1.
// ---------------------------------------------------------------------------
__global__ void __launch_bounds__(256, 2)
spatial_gemm_fp16(int dummy) {
    extern __shared__ __align__(1024) char smem[];
    const unsigned smem_base = smem_u32(smem);
    const int tid = threadIdx.x;
    const int n0 = blockIdx.x * BNF;   // filter base
    const int m0 = blockIdx.y * BM;    // bt base
    const __half* wmat = blockIdx.z ? wc_h : ws_h;
    __half* gout = blockIdx.z ? g_buf1 : g_buf0;

    const int lane = tid & 31;
    const int warp = tid >> 5;
    const int wm = (warp & 1) * 64;
    const int wn = (warp >> 1) * 32;

    float acc[4][4][4];
    #pragma unroll
    for (int i = 0; i < 4; i++)
        #pragma unroll
        for (int j = 0; j < 4; j++)
            #pragma unroll
            for (int k = 0; k < 4; k++) acc[i][j][k] = 0.f;

    // loader: row = tid>>2 (0..63, +64), seg = tid&3 (16B each); 2 xfers/array
    const int lrow = tid >> 2;
    const int seg = tid & 3;
    const __half* ga = x_h  + (size_t)(m0 + lrow) * HWDIM + seg * 8;
    const __half* gb = wmat + (size_t)(n0 + lrow) * HWDIM + seg * 8;
    const unsigned lsm = smem_base + lrow * PADROWB + seg * 16;

    auto load_stage = [&](int kt, int slot) {
        const unsigned sb = lsm + slot * STG_BYTES;
        const __half* pa = ga + kt * KC;
        const __half* pb = gb + kt * KC;
        #pragma unroll
        for (int i = 0; i < 2; i++) {
            cp_async16(sb + OFF_A + i * 64 * PADROWB, pa + (size_t)i * 64 * HWDIM);
            cp_async16(sb + OFF_B + i * 64 * PADROWB, pb + (size_t)i * 64 * HWDIM);
        }
        asm volatile("cp.async.commit_group;\n");
    };

    // ldmatrix per-lane byte offsets within a stage
    const int mrow = wm + (lane & 7) + 8 * ((lane >> 3) & 1);
    const int akb  = (lane >> 4) * 16;
    unsigned aoff[4];
    #pragma unroll
    for (int mt = 0; mt < 4; mt++) aoff[mt] = (mrow + mt * 16) * PADROWB + akb;

    const int nrow = wn + (lane & 7) + 8 * (lane >> 4);
    const int bkb  = ((lane >> 3) & 1) * 16;
    unsigned boff[2];
    #pragma unroll
    for (int p = 0; p < 2; p++) boff[p] = (nrow + p * 16) * PADROWB + bkb;

    // prologue
    load_stage(0, 0);
    load_stage(1, 1);

    for (int kt = 0; kt < NCHUNK; kt++) {
        if (kt < NCHUNK - 1) asm volatile("cp.async.wait_group 1;\n");
        else                 asm volatile("cp.async.wait_group 0;\n");
        __syncthreads();
        if (kt + 2 < NCHUNK) load_stage(kt + 2, (kt + 2) % 3);

        const unsigned sb = smem_base + (kt % 3) * STG_BYTES;
        #pragma unroll
        for (int kk = 0; kk < 2; kk++) {
            const unsigned kb = kk * 32;
            uint32_t a[4][4], b[2][4];
            #pragma unroll
            for (int mt = 0; mt < 4; mt++) ldsm_x4(a[mt], sb + OFF_A + aoff[mt] + kb);
            #pragma unroll
            for (int p = 0; p < 2; p++) ldsm_x4(b[p], sb + OFF_B + boff[p] + kb);
            #pragma unroll
            for (int mt = 0; mt < 4; mt++)
                #pragma unroll
                for (int nt = 0; nt < 4; nt++)
                    mma_fp16(acc[mt][nt], a[mt], &b[nt >> 1][(nt & 1) * 2]);
        }
        __syncthreads();
    }

    // epilogue: fp16 output (half2 per row-pair)
    #pragma unroll
    for (int mt = 0; mt < 4; mt++) {
        #pragma unroll
        for (int nt = 0; nt < 4; nt++) {
            int m = m0 + wm + mt * 16 + (lane >> 2);
            int n = n0 + wn + nt * 8 + (lane & 3) * 2;
            *reinterpret_cast<__half2*>(&gout[(size_t)m * NF + n]) =
                __floats2half2_rn(acc[mt][nt][0], acc[mt][nt][1]);
            *reinterpret_cast<__half2*>(&gout[(size_t)(m + 8) * NF + n]) =
                __floats2half2_rn(acc[mt][nt][2], acc[mt][nt][3]);
        }
    }
}

// ---------------------------------------------------------------------------
// Kernel 2: depthwise temporal convs + energy, 3-multiply complex form.
//   m1 = sum (gc+gs)*wtc,  m2 = sum gc*(wts-wtc),  m3 = sum gs*(wtc+wts)
//   resp_sin = m1 + m2,  resp_cos = m1 - m3
// fp16 g input; ring-buffer window, T in 15 chunks of 16.
// ---------------------------------------------------------------------------
__global__ void __launch_bounds__(256)
temporal_kernel(const float* __restrict__ wt_sin_g,
                const float* __restrict__ wt_cos_g,
                float* __restrict__ out) {
    const int f = blockIdx.x * 256 + threadIdx.x;
    const int b = blockIdx.y;
    const int t0 = blockIdx.z * TCH;

    float wtc[TW], wd[TW], w1[TW];
    #pragma unroll
    for (int j = 0; j < TW; j++) {
        float s = wt_sin_g[f * TW + j];
        float c = wt_cos_g[f * TW + j];
        wtc[j] = c;
        wd[j]  = s - c;     // wts - wtc
        w1[j]  = c + s;     // wtc + wts
    }

    const __half* gs = g_buf0 + (size_t)b * T_LEN * NF + f;
    const __half* gc = g_buf1 + (size_t)b * T_LEN * NF + f;
    float* op = out + (size_t)b * T_LEN * NF + f;

    // rings: rs = g_sin, rc = g_cos, rq = g_cos + g_sin (amortized sum)
    float rs[TW], rc[TW], rq[TW];
    #pragma unroll
    for (int j = 0; j < TW; j++) {
        int t = t0 - 8 + j;
        int i = t & 15;
        float vs = (t >= 0) ? __half2float(gs[t * NF]) : 0.f;
        float vc = (t >= 0) ? __half2float(gc[t * NF]) : 0.f;
        rs[i] = vs; rc[i] = vc; rq[i] = vc + vs;
    }

    #pragma unroll
    for (int tt = 0; tt < TCH; tt++) {
        const int t = t0 + tt;
        float m1 = 0.f, m2 = 0.f, m3 = 0.f;
        #pragma unroll
        for (int j = 0; j < TW; j++) {
            int i = (tt - 8 + j) & 15;     // t0 % 16 == 0 -> static indices
            m1 += rq[i] * wtc[j];
            m2 += rc[i] * wd[j];
            m3 += rs[i] * w1[j];
        }
        float resp_s = m1 + m2;
        float resp_c = m1 - m3;
        float v = resp_s * resp_s + resp_c * resp_c;
        op[t * NF] = __logf(sqrtf(v) + 1e-5f);

        int tn = t + 8;
        int i = tn & 15;
        float vs = (tn < T_LEN) ? __half2float(gs[tn * NF]) : 0.f;
        float vc = (tn < T_LEN) ? __half2float(gc[tn * NF]) : 0.f;
        rs[i] = vs; rc[i] = vc; rq[i] = vc + vs;
    }
}

extern "C" void kernel_launch(void* const* d_in, const int* in_sizes, int n_in,
                              void* d_out, int out_size) {
    const float* x       = (const float*)d_in[0];
    const float* w_s_sin = (const float*)d_in[1];
    const float* w_s_cos = (const float*)d_in[2];
    const float* w_t_sin = (const float*)d_in[3];
    const float* w_t_cos = (const float*)d_in[4];
    float* out = (float*)d_out;

    f2h_all_kernel<<<(NQ4 + 255) / 256, 256>>>(x, w_s_sin, w_s_cos);

    cudaFuncSetAttribute(spatial_gemm_fp16,
                         cudaFuncAttributeMaxDynamicSharedMemorySize, SMEM_DYN);

    dim3 g1(NF / BNF, BT / BM, 2);     // (20, 15, 2) = 600 CTAs, 2/SM
    spatial_gemm_fp16<<<g1, 256, SMEM_DYN>>>(0);

    dim3 g2(NF / 256, BATCH, T_LEN / TCH);   // (10, 8, 15) = 1200 blocks
    temporal_kernel<<<g2, 256>>>(w_t_sin, w_t_cos, out);
}

// round 15
// speedup vs baseline: 1.0912x; 1.0204x over previous
#include <cuda_runtime.h>
#include <cuda_fp16.h>
#include <cstdint>

#define NF      2560
#define TW      16
#define HWDIM   9216
#define BT      1920
#define T_LEN   240
#define BATCH   8

#define BM      128     // bt rows per CTA (M)
#define BNF     128     // filters per CTA (N)
#define KC      32      // K elements per stage
#define NCHUNK  288     // HWDIM / KC
#define NSTAGE  5
#define PADROWB 80      // bytes per smem row (32 halves = 64B + 16B pad)
#define OFF_A   0
#define OFF_B   (128 * PADROWB)          // 10240
#define STG_BYTES (256 * PADROWB)        // 20480
#define SMEM_DYN  (NSTAGE * STG_BYTES)   // 102400

#define TCH     16      // temporal chunk length

// fp16 copies of inputs (filled by convert kernel)
__device__ __half x_h[BT * HWDIM];
__device__ __half ws_h[NF * HWDIM];
__device__ __half wc_h[NF * HWDIM];
// intermediate g_sin / g_cos in fp16, layout [bt][f]
__device__ __half g_buf0[BT * NF];
__device__ __half g_buf1[BT * NF];

// ---------------------------------------------------------------------------
__device__ __forceinline__ unsigned smem_u32(const void* p) {
    return (unsigned)__cvta_generic_to_shared(p);
}
__device__ __forceinline__ void cp_async16(unsigned saddr, const void* gaddr) {
    asm volatile("cp.async.cg.shared.global [%0], [%1], 16;\n" :: "r"(saddr), "l"(gaddr));
}
__device__ __forceinline__ void ldsm_x4(uint32_t* r, unsigned addr) {
    asm volatile("ldmatrix.sync.aligned.m8n8.x4.shared.b16 {%0,%1,%2,%3}, [%4];"
                 : "=r"(r[0]), "=r"(r[1]), "=r"(r[2]), "=r"(r[3]) : "r"(addr));
}
__device__ __forceinline__ void mma_fp16(float* c, const uint32_t* a, const uint32_t* b) {
    asm volatile(
        "mma.sync.aligned.m16n8k16.row.col.f32.f16.f16.f32 "
        "{%0,%1,%2,%3}, {%4,%5,%6,%7}, {%8,%9}, {%0,%1,%2,%3};\n"
        : "+f"(c[0]), "+f"(c[1]), "+f"(c[2]), "+f"(c[3])
        : "r"(a[0]), "r"(a[1]), "r"(a[2]), "r"(a[3]), "r"(b[0]), "r"(b[1]));
}

// ---------------------------------------------------------------------------
// Kernel 0: fp32 -> fp16 conversion for x, w_s_sin, w_s_cos in ONE launch.
// 4 independent float4 per thread (MLP=4).
// ---------------------------------------------------------------------------
#define NX4 (BT * HWDIM / 4)             // 4423680
#define NW4 (NF * HWDIM / 4)             // 5898240
#define NTOT4 (NX4 + 2 * NW4)            // 16220160
#define NQ4   (NTOT4 / 4)                // 4055040

__device__ __forceinline__ void f2h_one(int j,
                                        const float* __restrict__ x,
                                        const float* __restrict__ wsin,
                                        const float* __restrict__ wcos) {
    const float* src;
    __half* dst;
    if (j < NX4)                { src = x;    dst = x_h; }
    else if (j < NX4 + NW4)     { src = wsin; dst = ws_h; j -= NX4; }
    else                        { src = wcos; dst = wc_h; j -= NX4 + NW4; }
    float4 v = reinterpret_cast<const float4*>(src)[j];
    reinterpret_cast<__half2*>(dst)[2 * j]     = __floats2half2_rn(v.x, v.y);
    reinterpret_cast<__half2*>(dst)[2 * j + 1] = __floats2half2_rn(v.z, v.w);
}

__global__ void __launch_bounds__(256)
f2h_all_kernel(const float* __restrict__ x,
               const float* __restrict__ wsin,
               const float* __restrict__ wcos) {
    int i = blockIdx.x * 256 + threadIdx.x;
    if (i < NQ4) {
        f2h_one(i, x, wsin, wcos);
        f2h_one(i + NQ4, x, wsin, wcos);
        f2h_one(i + 2 * NQ4, x, wsin, wcos);
        f2h_one(i + 3 * NQ4, x, wsin, wcos);
    }
}

// ---------------------------------------------------------------------------
// Kernel 1: spatial GEMM, fp16 mma.sync, KC=32, 5-stage cp.async (wait 3),
// 2 CTAs/SM, R4 2-barrier loop structure (proven best of 9 variants).
//   g[m, f] = sum_k x[m,k] * w[f,k]   (output stored fp16)
// Block tile 128(m) x 128(f), 256 threads, warp tile 64m x 32f.
// blockIdx.z: 0 -> ws_h -> g_buf0, 1 -> wc_h -> g_buf1.
// ---------------------------------------------------------------------------
__global__ void __launch_bounds__(256, 2)
spatial_gemm_fp16(int dummy) {
    extern __shared__ __align__(1024) char smem[];
    const unsigned smem_base = smem_u32(smem);
    const int tid = threadIdx.x;
    const int n0 = blockIdx.x * BNF;   // filter base
    const int m0 = blockIdx.y * BM;    // bt base
    const __half* wmat = blockIdx.z ? wc_h : ws_h;
    __half* gout = blockIdx.z ? g_buf1 : g_buf0;

    const int lane = tid & 31;
    const int warp = tid >> 5;
    const int wm = (warp & 1) * 64;
    const int wn = (warp >> 1) * 32;

    float acc[4][4][4];
    #pragma unroll
    for (int i = 0; i < 4; i++)
        #pragma unroll
        for (int j = 0; j < 4; j++)
            #pragma unroll
            for (int k = 0; k < 4; k++) acc[i][j][k] = 0.f;

    // loader: row = tid>>2 (0..63, +64), seg = tid&3 (16B each); 2 xfers/array
    const int lrow = tid >> 2;
    const int seg = tid & 3;
    const __half* ga = x_h  + (size_t)(m0 + lrow) * HWDIM + seg * 8;
    const __half* gb = wmat + (size_t)(n0 + lrow) * HWDIM + seg * 8;
    const unsigned lsm = smem_base + lrow * PADROWB + seg * 16;

    auto load_stage = [&](int kt, int slot) {
        const unsigned sb = lsm + slot * STG_BYTES;
        const __half* pa = ga + kt * KC;
        const __half* pb = gb + kt * KC;
        #pragma unroll
        for (int i = 0; i < 2; i++) {
            cp_async16(sb + OFF_A + i * 64 * PADROWB, pa + (size_t)i * 64 * HWDIM);
            cp_async16(sb + OFF_B + i * 64 * PADROWB, pb + (size_t)i * 64 * HWDIM);
        }
        asm volatile("cp.async.commit_group;\n");
    };

    // ldmatrix per-lane byte offsets within a stage
    const int mrow = wm + (lane & 7) + 8 * ((lane >> 3) & 1);
    const int akb  = (lane >> 4) * 16;
    unsigned aoff[4];
    #pragma unroll
    for (int mt = 0; mt < 4; mt++) aoff[mt] = (mrow + mt * 16) * PADROWB + akb;

    const int nrow = wn + (lane & 7) + 8 * (lane >> 4);
    const int bkb  = ((lane >> 3) & 1) * 16;
    unsigned boff[2];
    #pragma unroll
    for (int p = 0; p < 2; p++) boff[p] = (nrow + p * 16) * PADROWB + bkb;

    // prologue: fill 4 of 5 stages
    load_stage(0, 0);
    load_stage(1, 1);
    load_stage(2, 2);
    load_stage(3, 3);

    for (int kt = 0; kt < NCHUNK; kt++) {
        // keep up to 3 groups in flight; stage kt is complete after this wait
        const int inflight = NCHUNK - 1 - kt;   // loads not yet issued come later
        if (inflight >= 3)      asm volatile("cp.async.wait_group 3;\n");
        else if (inflight == 2) asm volatile("cp.async.wait_group 2;\n");
        else if (inflight == 1) asm volatile("cp.async.wait_group 1;\n");
        else                    asm volatile("cp.async.wait_group 0;\n");
        __syncthreads();
        if (kt + 4 < NCHUNK) load_stage(kt + 4, (kt + 4) % NSTAGE);

        const unsigned sb = smem_base + (kt % NSTAGE) * STG_BYTES;
        #pragma unroll
        for (int kk = 0; kk < 2; kk++) {
            const unsigned kb = kk * 32;
            uint32_t a[4][4], b[2][4];
            #pragma unroll
            for (int mt = 0; mt < 4; mt++) ldsm_x4(a[mt], sb + OFF_A + aoff[mt] + kb);
            #pragma unroll
            for (int p = 0; p < 2; p++) ldsm_x4(b[p], sb + OFF_B + boff[p] + kb);
            #pragma unroll
            for (int mt = 0; mt < 4; mt++)
                #pragma unroll
                for (int nt = 0; nt < 4; nt++)
                    mma_fp16(acc[mt][nt], a[mt], &b[nt >> 1][(nt & 1) * 2]);
        }
        __syncthreads();   // WAR guard: load at iter kt+1 targets slot (kt)%5
    }

    // epilogue: fp16 output (half2 per row-pair)
    #pragma unroll
    for (int mt = 0; mt < 4; mt++) {
        #pragma unroll
        for (int nt = 0; nt < 4; nt++) {
            int m = m0 + wm + mt * 16 + (lane >> 2);
            int n = n0 + wn + nt * 8 + (lane & 3) * 2;
            *reinterpret_cast<__half2*>(&gout[(size_t)m * NF + n]) =
                __floats2half2_rn(acc[mt][nt][0], acc[mt][nt][1]);
            *reinterpret_cast<__half2*>(&gout[(size_t)(m + 8) * NF + n]) =
                __floats2half2_rn(acc[mt][nt][2], acc[mt][nt][3]);
        }
    }
}

// ---------------------------------------------------------------------------
// Kernel 2: depthwise temporal convs + energy, 3-multiply complex form.
//   m1 = sum (gc+gs)*wtc,  m2 = sum gc*(wts-wtc),  m3 = sum gs*(wtc+wts)
//   resp_sin = m1 + m2,  resp_cos = m1 - m3
// fp16 g input; ring-buffer window, T in 15 chunks of 16.
// ---------------------------------------------------------------------------
__global__ void __launch_bounds__(256)
temporal_kernel(const float* __restrict__ wt_sin_g,
                const float* __restrict__ wt_cos_g,
                float* __restrict__ out) {
    const int f = blockIdx.x * 256 + threadIdx.x;
    const int b = blockIdx.y;
    const int t0 = blockIdx.z * TCH;

    float wtc[TW], wd[TW], w1[TW];
    #pragma unroll
    for (int j = 0; j < TW; j++) {
        float s = wt_sin_g[f * TW + j];
        float c = wt_cos_g[f * TW + j];
        wtc[j] = c;
        wd[j]  = s - c;     // wts - wtc
        w1[j]  = c + s;     // wtc + wts
    }

    const __half* gs = g_buf0 + (size_t)b * T_LEN * NF + f;
    const __half* gc = g_buf1 + (size_t)b * T_LEN * NF + f;
    float* op = out + (size_t)b * T_LEN * NF + f;

    // rings: rs = g_sin, rc = g_cos, rq = g_cos + g_sin (amortized sum)
    float rs[TW], rc[TW], rq[TW];
    #pragma unroll
    for (int j = 0; j < TW; j++) {
        int t = t0 - 8 + j;
        int i = t & 15;
        float vs = (t >= 0) ? __half2float(gs[t * NF]) : 0.f;
        float vc = (t >= 0) ? __half2float(gc[t * NF]) : 0.f;
        rs[i] = vs; rc[i] = vc; rq[i] = vc + vs;
    }

    #pragma unroll
    for (int tt = 0; tt < TCH; tt++) {
        const int t = t0 + tt;
        float m1 = 0.f, m2 = 0.f, m3 = 0.f;
        #pragma unroll
        for (int j = 0; j < TW; j++) {
            int i = (tt - 8 + j) & 15;     // t0 % 16 == 0 -> static indices
            m1 += rq[i] * wtc[j];
            m2 += rc[i] * wd[j];
            m3 += rs[i] * w1[j];
        }
        float resp_s = m1 + m2;
        float resp_c = m1 - m3;
        float v = resp_s * resp_s + resp_c * resp_c;
        op[t * NF] = __logf(sqrtf(v) + 1e-5f);

        int tn = t + 8;
        int i = tn & 15;
        float vs = (tn < T_LEN) ? __half2float(gs[tn * NF]) : 0.f;
        float vc = (tn < T_LEN) ? __half2float(gc[tn * NF]) : 0.f;
        rs[i] = vs; rc[i] = vc; rq[i] = vc + vs;
    }
}

extern "C" void kernel_launch(void* const* d_in, const int* in_sizes, int n_in,
                              void* d_out, int out_size) {
    const float* x       = (const float*)d_in[0];
    const float* w_s_sin = (const float*)d_in[1];
    const float* w_s_cos = (const float*)d_in[2];
    const float* w_t_sin = (const float*)d_in[3];
    const float* w_t_cos = (const float*)d_in[4];
    float* out = (float*)d_out;

    f2h_all_kernel<<<(NQ4 + 255) / 256, 256>>>(x, w_s_sin, w_s_cos);

    cudaFuncSetAttribute(spatial_gemm_fp16,
                         cudaFuncAttributeMaxDynamicSharedMemorySize, SMEM_DYN);

    dim3 g1(NF / BNF, BT / BM, 2);     // (20, 15, 2) = 600 CTAs, 2/SM
    spatial_gemm_fp16<<<g1, 256, SMEM_DYN>>>(0);

    dim3 g2(NF / 256, BATCH, T_LEN / TCH);   // (10, 8, 15) = 1200 blocks
    temporal_kernel<<<g2, 256>>>(w_t_sin, w_t_cos, out);
}

// round 16
// speedup vs baseline: 1.1012x; 1.0091x over previous
#include <cuda_runtime.h>
#include <cuda_fp16.h>
#include <cstdint>

#define NF      2560
#define TW      16
#define HWDIM   9216
#define BT      1920
#define T_LEN   240
#define BATCH   8

#define BM      128     // bt rows per CTA (M)
#define BNF     128     // filters per CTA (N)
#define KC      32      // K elements per stage
#define NCHUNK  288     // HWDIM / KC
#define NSTAGE  5
#define PADROWB 80      // bytes per smem row (32 halves = 64B + 16B pad)
#define OFF_A   0
#define OFF_B   (128 * PADROWB)          // 10240
#define STG_BYTES (256 * PADROWB)        // 20480
#define SMEM_DYN  (NSTAGE * STG_BYTES)   // 102400

#define TCH     16      // temporal chunk length

// fp16 copies of inputs (filled by convert kernel)
__device__ __half x_h[BT * HWDIM];
__device__ __half ws_h[NF * HWDIM];
__device__ __half wc_h[NF * HWDIM];
// intermediate g_sin / g_cos in fp16, layout [bt][f]
__device__ __half g_buf0[BT * NF];
__device__ __half g_buf1[BT * NF];

// ---------------------------------------------------------------------------
__device__ __forceinline__ unsigned smem_u32(const void* p) {
    return (unsigned)__cvta_generic_to_shared(p);
}
__device__ __forceinline__ void cp_async16(unsigned saddr, const void* gaddr) {
    asm volatile("cp.async.cg.shared.global [%0], [%1], 16;\n" :: "r"(saddr), "l"(gaddr));
}
__device__ __forceinline__ void ldsm_x4(uint32_t* r, unsigned addr) {
    asm volatile("ldmatrix.sync.aligned.m8n8.x4.shared.b16 {%0,%1,%2,%3}, [%4];"
                 : "=r"(r[0]), "=r"(r[1]), "=r"(r[2]), "=r"(r[3]) : "r"(addr));
}
__device__ __forceinline__ void mma_fp16(float* c, const uint32_t* a, const uint32_t* b) {
    asm volatile(
        "mma.sync.aligned.m16n8k16.row.col.f32.f16.f16.f32 "
        "{%0,%1,%2,%3}, {%4,%5,%6,%7}, {%8,%9}, {%0,%1,%2,%3};\n"
        : "+f"(c[0]), "+f"(c[1]), "+f"(c[2]), "+f"(c[3])
        : "r"(a[0]), "r"(a[1]), "r"(a[2]), "r"(a[3]), "r"(b[0]), "r"(b[1]));
}

// ---------------------------------------------------------------------------
// Kernel 0: fp32 -> fp16 conversion for x, w_s_sin, w_s_cos in ONE launch.
// 4 independent float4 per thread (MLP=4).
// ---------------------------------------------------------------------------
#define NX4 (BT * HWDIM / 4)             // 4423680
#define NW4 (NF * HWDIM / 4)             // 5898240
#define NTOT4 (NX4 + 2 * NW4)            // 16220160
#define NQ4   (NTOT4 / 4)                // 4055040

__device__ __forceinline__ void f2h_one(int j,
                                        const float* __restrict__ x,
                                        const float* __restrict__ wsin,
                                        const float* __restrict__ wcos) {
    const float* src;
    __half* dst;
    if (j < NX4)                { src = x;    dst = x_h; }
    else if (j < NX4 + NW4)     { src = wsin; dst = ws_h; j -= NX4; }
    else                        { src = wcos; dst = wc_h; j -= NX4 + NW4; }
    float4 v = reinterpret_cast<const float4*>(src)[j];
    reinterpret_cast<__half2*>(dst)[2 * j]     = __floats2half2_rn(v.x, v.y);
    reinterpret_cast<__half2*>(dst)[2 * j + 1] = __floats2half2_rn(v.z, v.w);
}

__global__ void __launch_bounds__(256)
f2h_all_kernel(const float* __restrict__ x,
               const float* __restrict__ wsin,
               const float* __restrict__ wcos) {
    int i = blockIdx.x * 256 + threadIdx.x;
    if (i < NQ4) {
        f2h_one(i, x, wsin, wcos);
        f2h_one(i + NQ4, x, wsin, wcos);
        f2h_one(i + 2 * NQ4, x, wsin, wcos);
        f2h_one(i + 3 * NQ4, x, wsin, wcos);
    }
}

// ---------------------------------------------------------------------------
// Kernel 1: spatial GEMM, fp16 mma.sync, KC=32, 5-stage cp.async (wait 3),
// 2 CTAs/SM, SINGLE barrier per iteration.
//   g[m, f] = sum_k x[m,k] * w[f,k]   (output stored fp16)
// Block tile 128(m) x 128(f), 256 threads, warp tile 64m x 32f.
// WAR safety: load issued after top barrier of iter kt targets slot
// (kt+4)%5 = (kt-1)%5; every warp past that barrier has completed
// compute(kt-1) in program order, so the slot is fully consumed.
// blockIdx.z: 0 -> ws_h -> g_buf0, 1 -> wc_h -> g_buf1.
// ---------------------------------------------------------------------------
__global__ void __launch_bounds__(256, 2)
spatial_gemm_fp16(int dummy) {
    extern __shared__ __align__(1024) char smem[];
    const unsigned smem_base = smem_u32(smem);
    const int tid = threadIdx.x;
    const int n0 = blockIdx.x * BNF;   // filter base
    const int m0 = blockIdx.y * BM;    // bt base
    const __half* wmat = blockIdx.z ? wc_h : ws_h;
    __half* gout = blockIdx.z ? g_buf1 : g_buf0;

    const int lane = tid & 31;
    const int warp = tid >> 5;
    const int wm = (warp & 1) * 64;
    const int wn = (warp >> 1) * 32;

    float acc[4][4][4];
    #pragma unroll
    for (int i = 0; i < 4; i++)
        #pragma unroll
        for (int j = 0; j < 4; j++)
            #pragma unroll
            for (int k = 0; k < 4; k++) acc[i][j][k] = 0.f;

    // loader: row = tid>>2 (0..63, +64), seg = tid&3 (16B each); 2 xfers/array
    const int lrow = tid >> 2;
    const int seg = tid & 3;
    const __half* ga = x_h  + (size_t)(m0 + lrow) * HWDIM + seg * 8;
    const __half* gb = wmat + (size_t)(n0 + lrow) * HWDIM + seg * 8;
    const unsigned lsm = smem_base + lrow * PADROWB + seg * 16;

    auto load_stage = [&](int kt, int slot) {
        const unsigned sb = lsm + slot * STG_BYTES;
        const __half* pa = ga + kt * KC;
        const __half* pb = gb + kt * KC;
        #pragma unroll
        for (int i = 0; i < 2; i++) {
            cp_async16(sb + OFF_A + i * 64 * PADROWB, pa + (size_t)i * 64 * HWDIM);
            cp_async16(sb + OFF_B + i * 64 * PADROWB, pb + (size_t)i * 64 * HWDIM);
        }
        asm volatile("cp.async.commit_group;\n");
    };

    // ldmatrix per-lane byte offsets within a stage
    const int mrow = wm + (lane & 7) + 8 * ((lane >> 3) & 1);
    const int akb  = (lane >> 4) * 16;
    unsigned aoff[4];
    #pragma unroll
    for (int mt = 0; mt < 4; mt++) aoff[mt] = (mrow + mt * 16) * PADROWB + akb;

    const int nrow = wn + (lane & 7) + 8 * (lane >> 4);
    const int bkb  = ((lane >> 3) & 1) * 16;
    unsigned boff[2];
    #pragma unroll
    for (int p = 0; p < 2; p++) boff[p] = (nrow + p * 16) * PADROWB + bkb;

    // prologue: fill 4 of 5 stages
    load_stage(0, 0);
    load_stage(1, 1);
    load_stage(2, 2);
    load_stage(3, 3);

    for (int kt = 0; kt < NCHUNK; kt++) {
        // keep up to 3 groups in flight; stage kt is complete after this wait
        const int inflight = NCHUNK - 1 - kt;
        if (inflight >= 3)      asm volatile("cp.async.wait_group 3;\n");
        else if (inflight == 2) asm volatile("cp.async.wait_group 2;\n");
        else if (inflight == 1) asm volatile("cp.async.wait_group 1;\n");
        else                    asm volatile("cp.async.wait_group 0;\n");
        __syncthreads();   // single barrier: stage kt ready + WAR guard
        if (kt + 4 < NCHUNK) load_stage(kt + 4, (kt + 4) % NSTAGE);

        const unsigned sb = smem_base + (kt % NSTAGE) * STG_BYTES;
        #pragma unroll
        for (int kk = 0; kk < 2; kk++) {
            const unsigned kb = kk * 32;
            uint32_t a[4][4], b[2][4];
            #pragma unroll
            for (int mt = 0; mt < 4; mt++) ldsm_x4(a[mt], sb + OFF_A + aoff[mt] + kb);
            #pragma unroll
            for (int p = 0; p < 2; p++) ldsm_x4(b[p], sb + OFF_B + boff[p] + kb);
            #pragma unroll
            for (int mt = 0; mt < 4; mt++)
                #pragma unroll
                for (int nt = 0; nt < 4; nt++)
                    mma_fp16(acc[mt][nt], a[mt], &b[nt >> 1][(nt & 1) * 2]);
        }
        // no bottom barrier (see WAR argument in header comment)
    }

    // epilogue: fp16 output (half2 per row-pair)
    #pragma unroll
    for (int mt = 0; mt < 4; mt++) {
        #pragma unroll
        for (int nt = 0; nt < 4; nt++) {
            int m = m0 + wm + mt * 16 + (lane >> 2);
            int n = n0 + wn + nt * 8 + (lane & 3) * 2;
            *reinterpret_cast<__half2*>(&gout[(size_t)m * NF + n]) =
                __floats2half2_rn(acc[mt][nt][0], acc[mt][nt][1]);
            *reinterpret_cast<__half2*>(&gout[(size_t)(m + 8) * NF + n]) =
                __floats2half2_rn(acc[mt][nt][2], acc[mt][nt][3]);
        }
    }
}

// ---------------------------------------------------------------------------
// Kernel 2: depthwise temporal convs + energy, 3-multiply complex form.
//   m1 = sum (gc+gs)*wtc,  m2 = sum gc*(wts-wtc),  m3 = sum gs*(wtc+wts)
//   resp_sin = m1 + m2,  resp_cos = m1 - m3
// fp16 g input; ring-buffer window, T in 15 chunks of 16.
// ---------------------------------------------------------------------------
__global__ void __launch_bounds__(256)
temporal_kernel(const float* __restrict__ wt_sin_g,
                const float* __restrict__ wt_cos_g,
                float* __restrict__ out) {
    const int f = blockIdx.x * 256 + threadIdx.x;
    const int b = blockIdx.y;
    const int t0 = blockIdx.z * TCH;

    float wtc[TW], wd[TW], w1[TW];
    #pragma unroll
    for (int j = 0; j < TW; j++) {
        float s = wt_sin_g[f * TW + j];
        float c = wt_cos_g[f * TW + j];
        wtc[j] = c;
        wd[j]  = s - c;     // wts - wtc
        w1[j]  = c + s;     // wtc + wts
    }

    const __half* gs = g_buf0 + (size_t)b * T_LEN * NF + f;
    const __half* gc = g_buf1 + (size_t)b * T_LEN * NF + f;
    float* op = out + (size_t)b * T_LEN * NF + f;

    // rings: rs = g_sin, rc = g_cos, rq = g_cos + g_sin (amortized sum)
    float rs[TW], rc[TW], rq[TW];
    #pragma unroll
    for (int j = 0; j < TW; j++) {
        int t = t0 - 8 + j;
        int i = t & 15;
        float vs = (t >= 0) ? __half2float(gs[t * NF]) : 0.f;
        float vc = (t >= 0) ? __half2float(gc[t * NF]) : 0.f;
        rs[i] = vs; rc[i] = vc; rq[i] = vc + vs;
    }

    #pragma unroll
    for (int tt = 0; tt < TCH; tt++) {
        const int t = t0 + tt;
        float m1 = 0.f, m2 = 0.f, m3 = 0.f;
        #pragma unroll
        for (int j = 0; j < TW; j++) {
            int i = (tt - 8 + j) & 15;     // t0 % 16 == 0 -> static indices
            m1 += rq[i] * wtc[j];
            m2 += rc[i] * wd[j];
            m3 += rs[i] * w1[j];
        }
        float resp_s = m1 + m2;
        float resp_c = m1 - m3;
        float v = resp_s * resp_s + resp_c * resp_c;
        op[t * NF] = __logf(sqrtf(v) + 1e-5f);

        int tn = t + 8;
        int i = tn & 15;
        float vs = (tn < T_LEN) ? __half2float(gs[tn * NF]) : 0.f;
        float vc = (tn < T_LEN) ? __half2float(gc[tn * NF]) : 0.f;
        rs[i] = vs; rc[i] = vc; rq[i] = vc + vs;
    }
}

extern "C" void kernel_launch(void* const* d_in, const int* in_sizes, int n_in,
                              void* d_out, int out_size) {
    const float* x       = (const float*)d_in[0];
    const float* w_s_sin = (const float*)d_in[1];
    const float* w_s_cos = (const float*)d_in[2];
    const float* w_t_sin = (const float*)d_in[3];
    const float* w_t_cos = (const float*)d_in[4];
    float* out = (float*)d_out;

    f2h_all_kernel<<<(NQ4 + 255) / 256, 256>>>(x, w_s_sin, w_s_cos);

    cudaFuncSetAttribute(spatial_gemm_fp16,
                         cudaFuncAttributeMaxDynamicSharedMemorySize, SMEM_DYN);

    dim3 g1(NF / BNF, BT / BM, 2);     // (20, 15, 2) = 600 CTAs, 2/SM
    spatial_gemm_fp16<<<g1, 256, SMEM_DYN>>>(0);

    dim3 g2(NF / 256, BATCH, T_LEN / TCH);   // (10, 8, 15) = 1200 blocks
    temporal_kernel<<<g2, 256>>>(w_t_sin, w_t_cos, out);
}

// round 17
// speedup vs baseline: 1.2439x; 1.1296x over previous
#include <cuda_runtime.h>
#include <cuda_fp16.h>
#include <cstdint>

#define NF      2560
#define TW      16
#define HWDIM   9216
#define BT      1920
#define T_LEN   240
#define BATCH   8

#define BM      128     // bt rows per CTA (M)
#define BNF     128     // filters per CTA (N)
#define KC      32      // K elements per stage
#define NCHUNK  288     // HWDIM / KC
#define NSTAGE  5
#define PADROWB 80      // bytes per smem row (32 halves = 64B + 16B pad)
#define OFF_A   0
#define OFF_B   (128 * PADROWB)          // 10240
#define STG_BYTES (256 * PADROWB)        // 20480
#define SMEM_DYN  (NSTAGE * STG_BYTES)   // 102400

#define TCH     16      // temporal chunk length

// fp16 copies of inputs (filled by convert kernel)
__device__ __half x_h[BT * HWDIM];
__device__ __half ws_h[NF * HWDIM];
__device__ __half wc_h[NF * HWDIM];
// intermediate g_sin / g_cos in fp16, layout [bt][f]
__device__ __half g_buf0[BT * NF];
__device__ __half g_buf1[BT * NF];

// ---------------------------------------------------------------------------
__device__ __forceinline__ unsigned smem_u32(const void* p) {
    return (unsigned)__cvta_generic_to_shared(p);
}
__device__ __forceinline__ void cp_async16(unsigned saddr, const void* gaddr) {
    asm volatile("cp.async.cg.shared.global [%0], [%1], 16;\n" :: "r"(saddr), "l"(gaddr));
}
__device__ __forceinline__ void ldsm_x4(uint32_t* r, unsigned addr) {
    asm volatile("ldmatrix.sync.aligned.m8n8.x4.shared.b16 {%0,%1,%2,%3}, [%4];"
                 : "=r"(r[0]), "=r"(r[1]), "=r"(r[2]), "=r"(r[3]) : "r"(addr));
}
__device__ __forceinline__ void mma_fp16(float* c, const uint32_t* a, const uint32_t* b) {
    asm volatile(
        "mma.sync.aligned.m16n8k16.row.col.f32.f16.f16.f32 "
        "{%0,%1,%2,%3}, {%4,%5,%6,%7}, {%8,%9}, {%0,%1,%2,%3};\n"
        : "+f"(c[0]), "+f"(c[1]), "+f"(c[2]), "+f"(c[3])
        : "r"(a[0]), "r"(a[1]), "r"(a[2]), "r"(a[3]), "r"(b[0]), "r"(b[1]));
}

// ---------------------------------------------------------------------------
// Kernel 0: fp32 -> fp16 conversion for x, w_s_sin, w_s_cos in ONE launch.
// 4 independent float4 per thread (MLP=4).
// ---------------------------------------------------------------------------
#define NX4 (BT * HWDIM / 4)             // 4423680
#define NW4 (NF * HWDIM / 4)             // 5898240
#define NTOT4 (NX4 + 2 * NW4)            // 16220160
#define NQ4   (NTOT4 / 4)                // 4055040

__device__ __forceinline__ void f2h_one(int j,
                                        const float* __restrict__ x,
                                        const float* __restrict__ wsin,
                                        const float* __restrict__ wcos) {
    const float* src;
    __half* dst;
    if (j < NX4)                { src = x;    dst = x_h; }
    else if (j < NX4 + NW4)     { src = wsin; dst = ws_h; j -= NX4; }
    else                        { src = wcos; dst = wc_h; j -= NX4 + NW4; }
    float4 v = reinterpret_cast<const float4*>(src)[j];
    reinterpret_cast<__half2*>(dst)[2 * j]     = __floats2half2_rn(v.x, v.y);
    reinterpret_cast<__half2*>(dst)[2 * j + 1] = __floats2half2_rn(v.z, v.w);
}

__global__ void __launch_bounds__(256)
f2h_all_kernel(const float* __restrict__ x,
               const float* __restrict__ wsin,
               const float* __restrict__ wcos) {
    int i = blockIdx.x * 256 + threadIdx.x;
    if (i < NQ4) {
        f2h_one(i, x, wsin, wcos);
        f2h_one(i + NQ4, x, wsin, wcos);
        f2h_one(i + 2 * NQ4, x, wsin, wcos);
        f2h_one(i + 3 * NQ4, x, wsin, wcos);
    }
}

// ---------------------------------------------------------------------------
// Kernel 1: spatial GEMM, fp16 mma.sync. 128 threads, 4 warps (2m x 2n),
// warp tile 64x64 (32KB LDSM/CTA-iter vs 48KB at 64x32), CTA tile 128x128,
// KC=32, 5-stage cp.async (wait 3), SINGLE barrier/iter, 2 CTAs/SM
// (256 thr/SM -> 255-reg cap, acc=128 fp32/thread fits without spill).
//   g[m, f] = sum_k x[m,k] * w[f,k]   (output stored fp16)
// blockIdx.z: 0 -> ws_h -> g_buf0, 1 -> wc_h -> g_buf1.
// ---------------------------------------------------------------------------
__global__ void __launch_bounds__(128, 2)
spatial_gemm_fp16(int dummy) {
    extern __shared__ __align__(1024) char smem[];
    const unsigned smem_base = smem_u32(smem);
    const int tid = threadIdx.x;
    const int n0 = blockIdx.x * BNF;   // filter base
    const int m0 = blockIdx.y * BM;    // bt base
    const __half* wmat = blockIdx.z ? wc_h : ws_h;
    __half* gout = blockIdx.z ? g_buf1 : g_buf0;

    const int lane = tid & 31;
    const int warp = tid >> 5;
    const int wm = (warp & 1) * 64;    // 2 m-warps
    const int wn = (warp >> 1) * 64;   // 2 n-warps

    float acc[4][8][4];
    #pragma unroll
    for (int i = 0; i < 4; i++)
        #pragma unroll
        for (int j = 0; j < 8; j++)
            #pragma unroll
            for (int k = 0; k < 4; k++) acc[i][j][k] = 0.f;

    // loader: 128 threads; row = tid>>2 (0..31, +32 x4), seg = tid&3 (16B)
    const int lrow = tid >> 2;
    const int seg = tid & 3;
    const __half* ga = x_h  + (size_t)(m0 + lrow) * HWDIM + seg * 8;
    const __half* gb = wmat + (size_t)(n0 + lrow) * HWDIM + seg * 8;
    const unsigned lsm = smem_base + lrow * PADROWB + seg * 16;

    auto load_stage = [&](int kt, int slot) {
        const unsigned sb = lsm + slot * STG_BYTES;
        const __half* pa = ga + kt * KC;
        const __half* pb = gb + kt * KC;
        #pragma unroll
        for (int i = 0; i < 4; i++) {
            cp_async16(sb + OFF_A + i * 32 * PADROWB, pa + (size_t)i * 32 * HWDIM);
            cp_async16(sb + OFF_B + i * 32 * PADROWB, pb + (size_t)i * 32 * HWDIM);
        }
        asm volatile("cp.async.commit_group;\n");
    };

    // ldmatrix per-lane byte offsets within a stage
    const int mrow = wm + (lane & 7) + 8 * ((lane >> 3) & 1);
    const int akb  = (lane >> 4) * 16;
    unsigned aoff[4];
    #pragma unroll
    for (int mt = 0; mt < 4; mt++) aoff[mt] = (mrow + mt * 16) * PADROWB + akb;

    const int nrow = wn + (lane & 7) + 8 * (lane >> 4);
    const int bkb  = ((lane >> 3) & 1) * 16;
    unsigned boff[4];
    #pragma unroll
    for (int p = 0; p < 4; p++) boff[p] = (nrow + p * 16) * PADROWB + bkb;

    // prologue: fill 4 of 5 stages
    load_stage(0, 0);
    load_stage(1, 1);
    load_stage(2, 2);
    load_stage(3, 3);

    for (int kt = 0; kt < NCHUNK; kt++) {
        const int inflight = NCHUNK - 1 - kt;
        if (inflight >= 3)      asm volatile("cp.async.wait_group 3;\n");
        else if (inflight == 2) asm volatile("cp.async.wait_group 2;\n");
        else if (inflight == 1) asm volatile("cp.async.wait_group 1;\n");
        else                    asm volatile("cp.async.wait_group 0;\n");
        __syncthreads();   // single barrier: stage kt ready + WAR guard
        if (kt + 4 < NCHUNK) load_stage(kt + 4, (kt + 4) % NSTAGE);

        const unsigned sb = smem_base + (kt % NSTAGE) * STG_BYTES;
        #pragma unroll
        for (int kk = 0; kk < 2; kk++) {
            const unsigned kb = kk * 32;
            uint32_t a[4][4], b[4][4];
            #pragma unroll
            for (int mt = 0; mt < 4; mt++) ldsm_x4(a[mt], sb + OFF_A + aoff[mt] + kb);
            #pragma unroll
            for (int p = 0; p < 4; p++)  ldsm_x4(b[p], sb + OFF_B + boff[p] + kb);
            #pragma unroll
            for (int mt = 0; mt < 4; mt++)
                #pragma unroll
                for (int nt = 0; nt < 8; nt++)
                    mma_fp16(acc[mt][nt], a[mt], &b[nt >> 1][(nt & 1) * 2]);
        }
        // no bottom barrier: load at iter kt+1 targets slot (kt)%5, consumed
        // by all warps before they pass the next top barrier
    }

    // epilogue: fp16 output (half2 per row-pair)
    #pragma unroll
    for (int mt = 0; mt < 4; mt++) {
        #pragma unroll
        for (int nt = 0; nt < 8; nt++) {
            int m = m0 + wm + mt * 16 + (lane >> 2);
            int n = n0 + wn + nt * 8 + (lane & 3) * 2;
            *reinterpret_cast<__half2*>(&gout[(size_t)m * NF + n]) =
                __floats2half2_rn(acc[mt][nt][0], acc[mt][nt][1]);
            *reinterpret_cast<__half2*>(&gout[(size_t)(m + 8) * NF + n]) =
                __floats2half2_rn(acc[mt][nt][2], acc[mt][nt][3]);
        }
    }
}

// ---------------------------------------------------------------------------
// Kernel 2: depthwise temporal convs + energy, 3-multiply complex form.
//   m1 = sum (gc+gs)*wtc,  m2 = sum gc*(wts-wtc),  m3 = sum gs*(wtc+wts)
//   resp_sin = m1 + m2,  resp_cos = m1 - m3
// fp16 g input; ring-buffer window, T in 15 chunks of 16.
// ---------------------------------------------------------------------------
__global__ void __launch_bounds__(256)
temporal_kernel(const float* __restrict__ wt_sin_g,
                const float* __restrict__ wt_cos_g,
                float* __restrict__ out) {
    const int f = blockIdx.x * 256 + threadIdx.x;
    const int b = blockIdx.y;
    const int t0 = blockIdx.z * TCH;

    float wtc[TW], wd[TW], w1[TW];
    #pragma unroll
    for (int j = 0; j < TW; j++) {
        float s = wt_sin_g[f * TW + j];
        float c = wt_cos_g[f * TW + j];
        wtc[j] = c;
        wd[j]  = s - c;     // wts - wtc
        w1[j]  = c + s;     // wtc + wts
    }

    const __half* gs = g_buf0 + (size_t)b * T_LEN * NF + f;
    const __half* gc = g_buf1 + (size_t)b * T_LEN * NF + f;
    float* op = out + (size_t)b * T_LEN * NF + f;

    // rings: rs = g_sin, rc = g_cos, rq = g_cos + g_sin (amortized sum)
    float rs[TW], rc[TW], rq[TW];
    #pragma unroll
    for (int j = 0; j < TW; j++) {
        int t = t0 - 8 + j;
        int i = t & 15;
        float vs = (t >= 0) ? __half2float(gs[t * NF]) : 0.f;
        float vc = (t >= 0) ? __half2float(gc[t * NF]) : 0.f;
        rs[i] = vs; rc[i] = vc; rq[i] = vc + vs;
    }

    #pragma unroll
    for (int tt = 0; tt < TCH; tt++) {
        const int t = t0 + tt;
        float m1 = 0.f, m2 = 0.f, m3 = 0.f;
        #pragma unroll
        for (int j = 0; j < TW; j++) {
            int i = (tt - 8 + j) & 15;     // t0 % 16 == 0 -> static indices
            m1 += rq[i] * wtc[j];
            m2 += rc[i] * wd[j];
            m3 += rs[i] * w1[j];
        }
        float resp_s = m1 + m2;
        float resp_c = m1 - m3;
        float v = resp_s * resp_s + resp_c * resp_c;
        op[t * NF] = __logf(sqrtf(v) + 1e-5f);

        int tn = t + 8;
        int i = tn & 15;
        float vs = (tn < T_LEN) ? __half2float(gs[tn * NF]) : 0.f;
        float vc = (tn < T_LEN) ? __half2float(gc[tn * NF]) : 0.f;
        rs[i] = vs; rc[i] = vc; rq[i] = vc + vs;
    }
}

extern "C" void kernel_launch(void* const* d_in, const int* in_sizes, int n_in,
                              void* d_out, int out_size) {
    const float* x       = (const float*)d_in[0];
    const float* w_s_sin = (const float*)d_in[1];
    const float* w_s_cos = (const float*)d_in[2];
    const float* w_t_sin = (const float*)d_in[3];
    const float* w_t_cos = (const float*)d_in[4];
    float* out = (float*)d_out;

    f2h_all_kernel<<<(NQ4 + 255) / 256, 256>>>(x, w_s_sin, w_s_cos);

    cudaFuncSetAttribute(spatial_gemm_fp16,
                         cudaFuncAttributeMaxDynamicSharedMemorySize, SMEM_DYN);

    dim3 g1(NF / BNF, BT / BM, 2);     // (20, 15, 2) = 600 CTAs, 2/SM
    spatial_gemm_fp16<<<g1, 128, SMEM_DYN>>>(0);

    dim3 g2(NF / 256, BATCH, T_LEN / TCH);   // (10, 8, 15) = 1200 blocks
    temporal_kernel<<<g2, 256>>>(w_t_sin, w_t_cos, out);
}